// round 14
// baseline (speedup 1.0000x reference)
#include <cuda_runtime.h>
#include <cuda_fp16.h>
#include <cstdint>

#define HIDDEN 2048
#define BATCH  16384
#define NUM_OPS 3

#define BM 128
#define BN 128
#define BK 64
#define NK (HIDDEN / BK)                  // 32
#define STAGES 3
#define A_STAGE_BYTES (BM * BK * 2)       // 16384
#define STAGE_BYTES ((BM + BN) * BK * 2)  // 32768
#define SMEM_BYTES (STAGES * STAGE_BYTES) // 98304
#define THREADS 128
#define GRID_Y 48

// ---- device scratch (static: allocation-free kernel_launch) ----
__device__ int    g_counts[NUM_OPS];
__device__ int    g_idx[NUM_OPS * BATCH];
// fp16 matrices, k-dim PERMUTED at b32-unit granularity within 16-elem groups:
// unit u stored at position p(u) = (u&~7) | ((u&3)<<1) | ((u>>2)&1)
__device__ __half g_xg[(size_t)NUM_OPS * BATCH * HIDDEN];
__device__ __half g_h [(size_t)NUM_OPS * BATCH * HIDDEN];
__device__ __half g_Wt1[(size_t)NUM_OPS * HIDDEN * HIDDEN]; // [e][n][h-perm]
__device__ __half g_Wt2[(size_t)NUM_OPS * HIDDEN * HIDDEN];

// ---- PTX helpers (base-target legal) ----
__device__ __forceinline__ uint32_t smem_u32(const void* p) {
    uint32_t a;
    asm("{ .reg .u64 t; cvta.to.shared.u64 t, %1; cvt.u32.u64 %0, t; }" : "=r"(a) : "l"(p));
    return a;
}
__device__ __forceinline__ void cp_async16(uint32_t saddr, const void* gaddr) {
    asm volatile("cp.async.cg.shared.global [%0], [%1], 16;" :: "r"(saddr), "l"(gaddr) : "memory");
}
__device__ __forceinline__ void cp_commit() {
    asm volatile("cp.async.commit_group;" ::: "memory");
}
template<int N> __device__ __forceinline__ void cp_wait() {
    asm volatile("cp.async.wait_group %0;" :: "n"(N) : "memory");
}
__device__ __forceinline__ uint2 lds_u32x2(uint32_t addr) {
    uint2 v;
    asm volatile("ld.shared.v2.b32 {%0,%1}, [%2];" : "=r"(v.x), "=r"(v.y) : "r"(addr));
    return v;
}
__device__ __forceinline__ void mma_f16(float* c, uint32_t a0, uint32_t a1,
                                        uint32_t a2, uint32_t a3,
                                        uint32_t b0, uint32_t b1) {
    asm volatile(
        "mma.sync.aligned.m16n8k16.row.col.f32.f16.f16.f32 "
        "{%0,%1,%2,%3}, {%4,%5,%6,%7}, {%8,%9}, {%0,%1,%2,%3};"
        : "+f"(c[0]), "+f"(c[1]), "+f"(c[2]), "+f"(c[3])
        : "r"(a0), "r"(a1), "r"(a2), "r"(a3), "r"(b0), "r"(b1));
}
__device__ __forceinline__ uint32_t h2bits(float lo, float hi) {
    __half2 h = __floats2half2_rn(lo, hi);
    return *reinterpret_cast<uint32_t*>(&h);
}

// ---- prep kernels ----
__global__ void reset_kernel() {
    if (threadIdx.x < NUM_OPS) g_counts[threadIdx.x] = 0;
}
// bucket only: row -> packed slot (reads chosen, writes g_idx/g_counts)
__global__ void bucket_kernel(const int* __restrict__ chosen) {
    int i = blockIdx.x * blockDim.x + threadIdx.x;
    int e = chosen[i];
    int pos = atomicAdd(&g_counts[e], 1);
    g_idx[e * BATCH + pos] = i;
}
// per-expert gather: block = one packed slot of expert e; convert + k-permute.
__global__ void gather_expert_kernel(int e, const float* __restrict__ x) {
    const int pos = blockIdx.x;
    if (pos >= g_counts[e]) return;
    const int row = g_idx[e * BATCH + pos];
    const int g = threadIdx.x;              // 0..127, one 16-elem k-group
    const float4* src = (const float4*)(x + (size_t)row * HIDDEN + g * 16);
    float4 v0 = src[0], v1 = src[1], v2 = src[2], v3 = src[3];
    uint32_t u[8];
    u[0] = h2bits(v0.x, v0.y); u[1] = h2bits(v0.z, v0.w);
    u[2] = h2bits(v1.x, v1.y); u[3] = h2bits(v1.z, v1.w);
    u[4] = h2bits(v2.x, v2.y); u[5] = h2bits(v2.z, v2.w);
    u[6] = h2bits(v3.x, v3.y); u[7] = h2bits(v3.z, v3.w);
    uint4 w0 = make_uint4(u[0], u[4], u[1], u[5]);
    uint4 w1 = make_uint4(u[2], u[6], u[3], u[7]);
    uint4* d = (uint4*)(g_xg + (size_t)(e * BATCH + pos) * HIDDEN + g * 16);
    d[0] = w0; d[1] = w1;
}
// Wt[e][n][perm-units of h] = fp16(W[e][h][n]) ; 64x64 tiles, 256 threads
__global__ void transpose_kernel(const float* __restrict__ W, __half* __restrict__ Wt) {
    __shared__ float t[64][65];
    const int e = blockIdx.z;
    const float* Win = W + (size_t)e * HIDDEN * HIDDEN;
    __half* Wout = Wt + (size_t)e * HIDDEN * HIDDEN;
    const int n0 = blockIdx.x * 64, h0 = blockIdx.y * 64;
    const int tid = threadIdx.x;
    #pragma unroll
    for (int i = 0; i < 4; i++) {
        int lin = tid + i * 256;
        int hr  = lin >> 4;
        int c4  = (lin & 15) * 4;
        float4 v = *(const float4*)(Win + (size_t)(h0 + hr) * HIDDEN + n0 + c4);
        t[hr][c4 + 0] = v.x; t[hr][c4 + 1] = v.y;
        t[hr][c4 + 2] = v.z; t[hr][c4 + 3] = v.w;
    }
    __syncthreads();
    const int n = tid & 63, g = tid >> 6;
    uint32_t u[8];
    #pragma unroll
    for (int j = 0; j < 8; j++)
        u[j] = h2bits(t[g * 16 + 2 * j][n], t[g * 16 + 2 * j + 1][n]);
    uint4 w0 = make_uint4(u[0], u[4], u[1], u[5]);
    uint4 w1 = make_uint4(u[2], u[6], u[3], u[7]);
    uint4* dst = (uint4*)(Wout + (size_t)(n0 + n) * HIDDEN + h0 + g * 16);
    dst[0] = w0; dst[1] = w1;
}

// ---- fp16 m16n8k16 GEMM, 4 warps/CTA, 64x64 warp tiles (R9 optimum) ----
// Per-expert launch: e is a kernel argument; grid = (16, GRID_Y).
template<bool FIRST>
__global__ void __launch_bounds__(THREADS, 2)
gemm_mma_kernel(int e,
                const __half* __restrict__ A,
                const __half* __restrict__ Wt,
                const float* __restrict__ bias,
                void* __restrict__ OutV)
{
    const int cnt = g_counts[e];
    const int n0  = blockIdx.x * BN;

    extern __shared__ char smem[];
    const uint32_t sbase = smem_u32(smem);

    const int tid  = threadIdx.x;
    const int lane = tid & 31;
    const int wid  = tid >> 5;
    const int wm   = wid >> 1;
    const int wn   = wid & 1;
    const int fr = lane >> 2;
    const int fc = lane & 3;
    const int a_r0 = wm * 64 + fr;
    const int b_r0 = wn * 64 + fr;

    const __half* Bbase = Wt + (size_t)e * HIDDEN * HIDDEN + (size_t)n0 * HIDDEN;

    auto vaddr = [](uint32_t tb, int r, int g, int fc_) -> uint32_t {
        return tb + (uint32_t)(r * 128) + (uint32_t)((((g * 4 + fc_) ^ ((r & 3) * 4)) << 3));
    };

    float bv[8][2];
    #pragma unroll
    for (int j = 0; j < 8; j++) {
        int col = n0 + wn * 64 + j * 8 + 2 * fc;
        bv[j][0] = bias[e * HIDDEN + col];
        bv[j][1] = bias[e * HIDDEN + col + 1];
    }

    for (int m0 = blockIdx.y * BM; m0 < cnt; m0 += GRID_Y * BM) {
        const __half* Abase = A + (size_t)(e * BATCH + m0) * HIDDEN;

        float acc[4][8][4];
        #pragma unroll
        for (int i = 0; i < 4; i++)
            #pragma unroll
            for (int j = 0; j < 8; j++)
                #pragma unroll
                for (int q = 0; q < 4; q++) acc[i][j][q] = 0.f;

        auto load_stage = [&](int s, int kt) {
            const uint32_t sa = sbase + s * STAGE_BYTES;
            const uint32_t sb = sa + A_STAGE_BYTES;
            const int kcol = kt * BK;
            #pragma unroll
            for (int i = 0; i < 8; i++) {
                int lin = tid + i * THREADS;
                int row = lin >> 3;
                int q   = lin & 7;
                uint32_t soff = (uint32_t)(row * 128 + ((q ^ ((row & 3) * 2)) << 4));
                cp_async16(sa + soff, Abase + (size_t)row * HIDDEN + kcol + q * 8);
                cp_async16(sb + soff, Bbase + (size_t)row * HIDDEN + kcol + q * 8);
            }
            cp_commit();
        };

        auto compute_stage = [&](int s) {
            const uint32_t sa = sbase + s * STAGE_BYTES;
            const uint32_t sb = sa + A_STAGE_BYTES;
            #pragma unroll
            for (int g = 0; g < 4; g++) {
                uint2 alo[4], ahi[4], bf[8];
                #pragma unroll
                for (int i = 0; i < 4; i++) {
                    alo[i] = lds_u32x2(vaddr(sa, a_r0 + i * 16,     g, fc));
                    ahi[i] = lds_u32x2(vaddr(sa, a_r0 + i * 16 + 8, g, fc));
                }
                #pragma unroll
                for (int j = 0; j < 8; j++)
                    bf[j] = lds_u32x2(vaddr(sb, b_r0 + j * 8, g, fc));
                #pragma unroll
                for (int i = 0; i < 4; i++)
                    #pragma unroll
                    for (int j = 0; j < 8; j++)
                        mma_f16(acc[i][j], alo[i].x, ahi[i].x, alo[i].y, ahi[i].y,
                                bf[j].x, bf[j].y);
            }
        };

        load_stage(0, 0);
        for (int kt = 0; kt < NK; kt++) {
            if (kt + 1 < NK) {
                load_stage((kt + 1) % STAGES, kt + 1);
                cp_wait<1>();
            } else {
                cp_wait<0>();
            }
            __syncthreads();
            compute_stage(kt % STAGES);
            __syncthreads();
        }

        // ---- epilogue ----
        #pragma unroll
        for (int i = 0; i < 4; i++) {
            #pragma unroll
            for (int half = 0; half < 2; half++) {
                int rt = wm * 64 + i * 16 + half * 8 + fr;
                int m  = m0 + rt;
                if (m < cnt) {
                    if (FIRST) {
                        __half* op = (__half*)OutV + (size_t)(e * BATCH + m) * HIDDEN;
                        const int ubase = (n0 + wn * 64) >> 1;
                        #pragma unroll
                        for (int j2 = 0; j2 < 4; j2++) {
                            float v0e = fmaxf(acc[i][2*j2][half*2+0] + bv[2*j2][0], 0.f);
                            float v1e = fmaxf(acc[i][2*j2][half*2+1] + bv[2*j2][1], 0.f);
                            float v0o = fmaxf(acc[i][2*j2+1][half*2+0] + bv[2*j2+1][0], 0.f);
                            float v1o = fmaxf(acc[i][2*j2+1][half*2+1] + bv[2*j2+1][1], 0.f);
                            uint2 st;
                            st.x = h2bits(v0e, v1e);
                            st.y = h2bits(v0o, v1o);
                            int p = ubase + j2 * 8 + (fc << 1);
                            *reinterpret_cast<uint2*>((__half2*)op + p) = st;
                        }
                    } else {
                        size_t orow = (size_t)g_idx[e * BATCH + m];
                        float* op = (float*)OutV + orow * HIDDEN;
                        #pragma unroll
                        for (int j = 0; j < 8; j++) {
                            float v0 = fmaxf(acc[i][j][half*2+0] + bv[j][0], 0.f);
                            float v1 = fmaxf(acc[i][j][half*2+1] + bv[j][1], 0.f);
                            float2 v; v.x = v0; v.y = v1;
                            *reinterpret_cast<float2*>(op + n0 + wn*64 + j*8 + 2*fc) = v;
                        }
                    }
                }
            }
        }
        __syncthreads();
    }
}

extern "C" void kernel_launch(void* const* d_in, const int* in_sizes, int n_in,
                              void* d_out, int out_size) {
    const float* x      = (const float*)d_in[0];
    const float* W1     = (const float*)d_in[1];
    const float* b1     = (const float*)d_in[2];
    const float* W2     = (const float*)d_in[3];
    const float* b2     = (const float*)d_in[4];
    const int*   chosen = (const int*)d_in[5];
    float* out = (float*)d_out;
    (void)in_sizes; (void)n_in; (void)out_size;

    void *p_xg, *p_h, *p_wt1, *p_wt2;
    cudaGetSymbolAddress(&p_xg,  g_xg);
    cudaGetSymbolAddress(&p_h,   g_h);
    cudaGetSymbolAddress(&p_wt1, g_Wt1);
    cudaGetSymbolAddress(&p_wt2, g_Wt2);

    // Same 2 side streams as passing R13; 7 small events.
    static cudaStream_t s1 = nullptr, s2 = nullptr;
    static cudaEvent_t evF = nullptr, evT1 = nullptr, evT2 = nullptr;
    static cudaEvent_t evG0 = nullptr, evG1 = nullptr, evE1 = nullptr, evE2 = nullptr;
    if (!s1) {
        cudaStreamCreateWithFlags(&s1, cudaStreamNonBlocking);
        cudaStreamCreateWithFlags(&s2, cudaStreamNonBlocking);
        cudaEventCreateWithFlags(&evF,  cudaEventDisableTiming);
        cudaEventCreateWithFlags(&evT1, cudaEventDisableTiming);
        cudaEventCreateWithFlags(&evT2, cudaEventDisableTiming);
        cudaEventCreateWithFlags(&evG0, cudaEventDisableTiming);
        cudaEventCreateWithFlags(&evG1, cudaEventDisableTiming);
        cudaEventCreateWithFlags(&evE1, cudaEventDisableTiming);
        cudaEventCreateWithFlags(&evE2, cudaEventDisableTiming);
        cudaFuncSetAttribute(gemm_mma_kernel<true>,
                             cudaFuncAttributeMaxDynamicSharedMemorySize, SMEM_BYTES);
        cudaFuncSetAttribute(gemm_mma_kernel<false>,
                             cudaFuncAttributeMaxDynamicSharedMemorySize, SMEM_BYTES);
    }

    dim3 tg(HIDDEN / 64, HIDDEN / 64, NUM_OPS);
    dim3 grid(HIDDEN / BN, GRID_Y);

    // fork
    cudaEventRecord(evF, 0);
    cudaStreamWaitEvent(s1, evF, 0);
    cudaStreamWaitEvent(s2, evF, 0);

    // s1: trW1 ; s2: trW2   (run under bucket+gather0)
    transpose_kernel<<<tg, 256, 0, s1>>>(W1, (__half*)p_wt1);
    cudaEventRecord(evT1, s1);
    transpose_kernel<<<tg, 256, 0, s2>>>(W2, (__half*)p_wt2);
    cudaEventRecord(evT2, s2);

    // stream 0: reset -> bucket -> gather0 -> expert-0 pipeline
    reset_kernel<<<1, 32>>>();
    bucket_kernel<<<BATCH / 256, 256>>>(chosen);
    gather_expert_kernel<<<BATCH, THREADS>>>(0, x);
    cudaEventRecord(evG0, 0);

    cudaStreamWaitEvent(0, evT1, 0);
    gemm_mma_kernel<true ><<<grid, THREADS, SMEM_BYTES>>>(
        0, (const __half*)p_xg, (const __half*)p_wt1, b1, p_h);
    cudaStreamWaitEvent(0, evT2, 0);
    gemm_mma_kernel<false><<<grid, THREADS, SMEM_BYTES>>>(
        0, (const __half*)p_h, (const __half*)p_wt2, b2, out);

    // s1: gather1 (after gather0) -> expert-1 pipeline
    cudaStreamWaitEvent(s1, evG0, 0);
    gather_expert_kernel<<<BATCH, THREADS, 0, s1>>>(1, x);
    cudaEventRecord(evG1, s1);
    gemm_mma_kernel<true ><<<grid, THREADS, SMEM_BYTES, s1>>>(
        1, (const __half*)p_xg, (const __half*)p_wt1, b1, p_h);
    cudaStreamWaitEvent(s1, evT2, 0);
    gemm_mma_kernel<false><<<grid, THREADS, SMEM_BYTES, s1>>>(
        1, (const __half*)p_h, (const __half*)p_wt2, b2, out);
    cudaEventRecord(evE1, s1);

    // s2: gather2 (after gather1) -> expert-2 pipeline
    cudaStreamWaitEvent(s2, evG1, 0);
    gather_expert_kernel<<<BATCH, THREADS, 0, s2>>>(2, x);
    cudaStreamWaitEvent(s2, evT1, 0);
    gemm_mma_kernel<true ><<<grid, THREADS, SMEM_BYTES, s2>>>(
        2, (const __half*)p_xg, (const __half*)p_wt1, b1, p_h);
    gemm_mma_kernel<false><<<grid, THREADS, SMEM_BYTES, s2>>>(
        2, (const __half*)p_h, (const __half*)p_wt2, b2, out);
    cudaEventRecord(evE2, s2);

    // join
    cudaStreamWaitEvent(0, evE1, 0);
    cudaStreamWaitEvent(0, evE2, 0);
}

// round 15
// speedup vs baseline: 1.0155x; 1.0155x over previous
#include <cuda_runtime.h>
#include <cuda_fp16.h>
#include <cstdint>

#define HIDDEN 2048
#define BATCH  16384
#define NUM_OPS 3

#define BM 128
#define BN 128
#define BK 64
#define NK (HIDDEN / BK)                  // 32
#define STAGES 3
#define A_STAGE_BYTES (BM * BK * 2)       // 16384
#define STAGE_BYTES ((BM + BN) * BK * 2)  // 32768
#define SMEM_BYTES (STAGES * STAGE_BYTES) // 98304
#define THREADS 128
#define GRID_Y 48

// ---- device scratch (static: allocation-free kernel_launch) ----
__device__ int    g_counts[NUM_OPS];
__device__ int    g_idx[NUM_OPS * BATCH];
// fp16 matrices, k-dim PERMUTED at b32-unit granularity within 16-elem groups:
// unit u stored at position p(u) = (u&~7) | ((u&3)<<1) | ((u>>2)&1)
__device__ __half g_xg[(size_t)NUM_OPS * BATCH * HIDDEN];
__device__ __half g_h [(size_t)NUM_OPS * BATCH * HIDDEN];
__device__ __half g_Wt1[(size_t)NUM_OPS * HIDDEN * HIDDEN]; // [e][n][h-perm]
__device__ __half g_Wt2[(size_t)NUM_OPS * HIDDEN * HIDDEN];

// ---- PTX helpers (base-target legal) ----
__device__ __forceinline__ uint32_t smem_u32(const void* p) {
    uint32_t a;
    asm("{ .reg .u64 t; cvta.to.shared.u64 t, %1; cvt.u32.u64 %0, t; }" : "=r"(a) : "l"(p));
    return a;
}
__device__ __forceinline__ void cp_async16(uint32_t saddr, const void* gaddr) {
    asm volatile("cp.async.cg.shared.global [%0], [%1], 16;" :: "r"(saddr), "l"(gaddr) : "memory");
}
__device__ __forceinline__ void cp_commit() {
    asm volatile("cp.async.commit_group;" ::: "memory");
}
template<int N> __device__ __forceinline__ void cp_wait() {
    asm volatile("cp.async.wait_group %0;" :: "n"(N) : "memory");
}
__device__ __forceinline__ uint2 lds_u32x2(uint32_t addr) {
    uint2 v;
    asm volatile("ld.shared.v2.b32 {%0,%1}, [%2];" : "=r"(v.x), "=r"(v.y) : "r"(addr));
    return v;
}
__device__ __forceinline__ void mma_f16(float* c, uint32_t a0, uint32_t a1,
                                        uint32_t a2, uint32_t a3,
                                        uint32_t b0, uint32_t b1) {
    asm volatile(
        "mma.sync.aligned.m16n8k16.row.col.f32.f16.f16.f32 "
        "{%0,%1,%2,%3}, {%4,%5,%6,%7}, {%8,%9}, {%0,%1,%2,%3};"
        : "+f"(c[0]), "+f"(c[1]), "+f"(c[2]), "+f"(c[3])
        : "r"(a0), "r"(a1), "r"(a2), "r"(a3), "r"(b0), "r"(b1));
}
__device__ __forceinline__ uint32_t h2bits(float lo, float hi) {
    __half2 h = __floats2half2_rn(lo, hi);
    return *reinterpret_cast<uint32_t*>(&h);
}

// ---- prep kernels ----
__global__ void reset_kernel() {
    if (threadIdx.x < NUM_OPS) g_counts[threadIdx.x] = 0;
}
// fused bucket + gather: block = one row; loads issued before the atomic/barrier
// so the atomic's global round-trip overlaps the 8KB read burst.
__global__ void bucketgather_kernel(const float* __restrict__ x,
                                    const int* __restrict__ chosen) {
    __shared__ int s_dst;
    const int row = blockIdx.x;
    const int g = threadIdx.x;              // 0..127, one 16-elem k-group
    const float4* src = (const float4*)(x + (size_t)row * HIDDEN + g * 16);
    float4 v0 = src[0], v1 = src[1], v2 = src[2], v3 = src[3];

    if (g == 0) {
        int e = chosen[row];
        int pos = atomicAdd(&g_counts[e], 1);
        g_idx[e * BATCH + pos] = row;
        s_dst = e * BATCH + pos;
    }

    uint32_t u[8];
    u[0] = h2bits(v0.x, v0.y); u[1] = h2bits(v0.z, v0.w);
    u[2] = h2bits(v1.x, v1.y); u[3] = h2bits(v1.z, v1.w);
    u[4] = h2bits(v2.x, v2.y); u[5] = h2bits(v2.z, v2.w);
    u[6] = h2bits(v3.x, v3.y); u[7] = h2bits(v3.z, v3.w);
    uint4 w0 = make_uint4(u[0], u[4], u[1], u[5]);
    uint4 w1 = make_uint4(u[2], u[6], u[3], u[7]);

    __syncthreads();
    const int dst = s_dst;
    uint4* d = (uint4*)(g_xg + (size_t)dst * HIDDEN + g * 16);
    d[0] = w0; d[1] = w1;
}
// Wt[e][n][perm-units of h] = fp16(W[e][h][n]) ; 64x64 tiles, 256 threads
__global__ void transpose_kernel(const float* __restrict__ W, __half* __restrict__ Wt) {
    __shared__ float t[64][65];
    const int e = blockIdx.z;
    const float* Win = W + (size_t)e * HIDDEN * HIDDEN;
    __half* Wout = Wt + (size_t)e * HIDDEN * HIDDEN;
    const int n0 = blockIdx.x * 64, h0 = blockIdx.y * 64;
    const int tid = threadIdx.x;
    #pragma unroll
    for (int i = 0; i < 4; i++) {
        int lin = tid + i * 256;
        int hr  = lin >> 4;
        int c4  = (lin & 15) * 4;
        float4 v = *(const float4*)(Win + (size_t)(h0 + hr) * HIDDEN + n0 + c4);
        t[hr][c4 + 0] = v.x; t[hr][c4 + 1] = v.y;
        t[hr][c4 + 2] = v.z; t[hr][c4 + 3] = v.w;
    }
    __syncthreads();
    const int n = tid & 63, g = tid >> 6;
    uint32_t u[8];
    #pragma unroll
    for (int j = 0; j < 8; j++)
        u[j] = h2bits(t[g * 16 + 2 * j][n], t[g * 16 + 2 * j + 1][n]);
    uint4 w0 = make_uint4(u[0], u[4], u[1], u[5]);
    uint4 w1 = make_uint4(u[2], u[6], u[3], u[7]);
    uint4* dst = (uint4*)(Wout + (size_t)(n0 + n) * HIDDEN + h0 + g * 16);
    dst[0] = w0; dst[1] = w1;
}

// ---- fp16 m16n8k16 GEMM, 4 warps/CTA, 64x64 warp tiles (session optimum) ----
// Per-expert launch: e is a kernel argument; grid = (16, GRID_Y).
template<bool FIRST>
__global__ void __launch_bounds__(THREADS, 2)
gemm_mma_kernel(int e,
                const __half* __restrict__ A,
                const __half* __restrict__ Wt,
                const float* __restrict__ bias,
                void* __restrict__ OutV)
{
    const int cnt = g_counts[e];
    const int n0  = blockIdx.x * BN;

    extern __shared__ char smem[];
    const uint32_t sbase = smem_u32(smem);

    const int tid  = threadIdx.x;
    const int lane = tid & 31;
    const int wid  = tid >> 5;
    const int wm   = wid >> 1;
    const int wn   = wid & 1;
    const int fr = lane >> 2;
    const int fc = lane & 3;
    const int a_r0 = wm * 64 + fr;
    const int b_r0 = wn * 64 + fr;

    const __half* Bbase = Wt + (size_t)e * HIDDEN * HIDDEN + (size_t)n0 * HIDDEN;

    auto vaddr = [](uint32_t tb, int r, int g, int fc_) -> uint32_t {
        return tb + (uint32_t)(r * 128) + (uint32_t)((((g * 4 + fc_) ^ ((r & 3) * 4)) << 3));
    };

    float bv[8][2];
    #pragma unroll
    for (int j = 0; j < 8; j++) {
        int col = n0 + wn * 64 + j * 8 + 2 * fc;
        bv[j][0] = bias[e * HIDDEN + col];
        bv[j][1] = bias[e * HIDDEN + col + 1];
    }

    for (int m0 = blockIdx.y * BM; m0 < cnt; m0 += GRID_Y * BM) {
        const __half* Abase = A + (size_t)(e * BATCH + m0) * HIDDEN;

        float acc[4][8][4];
        #pragma unroll
        for (int i = 0; i < 4; i++)
            #pragma unroll
            for (int j = 0; j < 8; j++)
                #pragma unroll
                for (int q = 0; q < 4; q++) acc[i][j][q] = 0.f;

        auto load_stage = [&](int s, int kt) {
            const uint32_t sa = sbase + s * STAGE_BYTES;
            const uint32_t sb = sa + A_STAGE_BYTES;
            const int kcol = kt * BK;
            #pragma unroll
            for (int i = 0; i < 8; i++) {
                int lin = tid + i * THREADS;
                int row = lin >> 3;
                int q   = lin & 7;
                uint32_t soff = (uint32_t)(row * 128 + ((q ^ ((row & 3) * 2)) << 4));
                cp_async16(sa + soff, Abase + (size_t)row * HIDDEN + kcol + q * 8);
                cp_async16(sb + soff, Bbase + (size_t)row * HIDDEN + kcol + q * 8);
            }
            cp_commit();
        };

        auto compute_stage = [&](int s) {
            const uint32_t sa = sbase + s * STAGE_BYTES;
            const uint32_t sb = sa + A_STAGE_BYTES;
            #pragma unroll
            for (int g = 0; g < 4; g++) {
                uint2 alo[4], ahi[4], bf[8];
                #pragma unroll
                for (int i = 0; i < 4; i++) {
                    alo[i] = lds_u32x2(vaddr(sa, a_r0 + i * 16,     g, fc));
                    ahi[i] = lds_u32x2(vaddr(sa, a_r0 + i * 16 + 8, g, fc));
                }
                #pragma unroll
                for (int j = 0; j < 8; j++)
                    bf[j] = lds_u32x2(vaddr(sb, b_r0 + j * 8, g, fc));
                #pragma unroll
                for (int i = 0; i < 4; i++)
                    #pragma unroll
                    for (int j = 0; j < 8; j++)
                        mma_f16(acc[i][j], alo[i].x, ahi[i].x, alo[i].y, ahi[i].y,
                                bf[j].x, bf[j].y);
            }
        };

        load_stage(0, 0);
        for (int kt = 0; kt < NK; kt++) {
            if (kt + 1 < NK) {
                load_stage((kt + 1) % STAGES, kt + 1);
                cp_wait<1>();
            } else {
                cp_wait<0>();
            }
            __syncthreads();
            compute_stage(kt % STAGES);
            __syncthreads();
        }

        // ---- epilogue ----
        #pragma unroll
        for (int i = 0; i < 4; i++) {
            #pragma unroll
            for (int half = 0; half < 2; half++) {
                int rt = wm * 64 + i * 16 + half * 8 + fr;
                int m  = m0 + rt;
                if (m < cnt) {
                    if (FIRST) {
                        __half* op = (__half*)OutV + (size_t)(e * BATCH + m) * HIDDEN;
                        const int ubase = (n0 + wn * 64) >> 1;
                        #pragma unroll
                        for (int j2 = 0; j2 < 4; j2++) {
                            float v0e = fmaxf(acc[i][2*j2][half*2+0] + bv[2*j2][0], 0.f);
                            float v1e = fmaxf(acc[i][2*j2][half*2+1] + bv[2*j2][1], 0.f);
                            float v0o = fmaxf(acc[i][2*j2+1][half*2+0] + bv[2*j2+1][0], 0.f);
                            float v1o = fmaxf(acc[i][2*j2+1][half*2+1] + bv[2*j2+1][1], 0.f);
                            uint2 st;
                            st.x = h2bits(v0e, v1e);
                            st.y = h2bits(v0o, v1o);
                            int p = ubase + j2 * 8 + (fc << 1);
                            *reinterpret_cast<uint2*>((__half2*)op + p) = st;
                        }
                    } else {
                        size_t orow = (size_t)g_idx[e * BATCH + m];
                        float* op = (float*)OutV + orow * HIDDEN;
                        #pragma unroll
                        for (int j = 0; j < 8; j++) {
                            float v0 = fmaxf(acc[i][j][half*2+0] + bv[j][0], 0.f);
                            float v1 = fmaxf(acc[i][j][half*2+1] + bv[j][1], 0.f);
                            float2 v; v.x = v0; v.y = v1;
                            *reinterpret_cast<float2*>(op + n0 + wn*64 + j*8 + 2*fc) = v;
                        }
                    }
                }
            }
        }
        __syncthreads();
    }
}

extern "C" void kernel_launch(void* const* d_in, const int* in_sizes, int n_in,
                              void* d_out, int out_size) {
    const float* x      = (const float*)d_in[0];
    const float* W1     = (const float*)d_in[1];
    const float* b1     = (const float*)d_in[2];
    const float* W2     = (const float*)d_in[3];
    const float* b2     = (const float*)d_in[4];
    const int*   chosen = (const int*)d_in[5];
    float* out = (float*)d_out;
    (void)in_sizes; (void)n_in; (void)out_size;

    void *p_xg, *p_h, *p_wt1, *p_wt2;
    cudaGetSymbolAddress(&p_xg,  g_xg);
    cudaGetSymbolAddress(&p_h,   g_h);
    cudaGetSymbolAddress(&p_wt1, g_Wt1);
    cudaGetSymbolAddress(&p_wt2, g_Wt2);

    // 2 streams + 6 events: same footprint class as the passing R13.
    static cudaStream_t s1 = nullptr, s2 = nullptr;
    static cudaEvent_t evF = nullptr, evT1 = nullptr, evT2 = nullptr;
    static cudaEvent_t evG = nullptr, evE1 = nullptr, evE2 = nullptr;
    if (!s1) {
        cudaStreamCreateWithFlags(&s1, cudaStreamNonBlocking);
        cudaStreamCreateWithFlags(&s2, cudaStreamNonBlocking);
        cudaEventCreateWithFlags(&evF,  cudaEventDisableTiming);
        cudaEventCreateWithFlags(&evT1, cudaEventDisableTiming);
        cudaEventCreateWithFlags(&evT2, cudaEventDisableTiming);
        cudaEventCreateWithFlags(&evG,  cudaEventDisableTiming);
        cudaEventCreateWithFlags(&evE1, cudaEventDisableTiming);
        cudaEventCreateWithFlags(&evE2, cudaEventDisableTiming);
        cudaFuncSetAttribute(gemm_mma_kernel<true>,
                             cudaFuncAttributeMaxDynamicSharedMemorySize, SMEM_BYTES);
        cudaFuncSetAttribute(gemm_mma_kernel<false>,
                             cudaFuncAttributeMaxDynamicSharedMemorySize, SMEM_BYTES);
    }

    dim3 tg(HIDDEN / 64, HIDDEN / 64, NUM_OPS);
    dim3 grid(HIDDEN / BN, GRID_Y);

    // fork
    cudaEventRecord(evF, 0);
    cudaStreamWaitEvent(s1, evF, 0);
    cudaStreamWaitEvent(s2, evF, 0);

    // s1: trW1 -> expert-1 pipeline ; s2: trW2 -> expert-2 pipeline
    transpose_kernel<<<tg, 256, 0, s1>>>(W1, (__half*)p_wt1);
    cudaEventRecord(evT1, s1);
    transpose_kernel<<<tg, 256, 0, s2>>>(W2, (__half*)p_wt2);
    cudaEventRecord(evT2, s2);

    // stream 0: prep -> expert-0 pipeline
    reset_kernel<<<1, 32>>>();
    bucketgather_kernel<<<BATCH, THREADS>>>(x, chosen);
    cudaEventRecord(evG, 0);

    // expert 0 on stream 0
    cudaStreamWaitEvent(0, evT1, 0);
    gemm_mma_kernel<true ><<<grid, THREADS, SMEM_BYTES>>>(
        0, (const __half*)p_xg, (const __half*)p_wt1, b1, p_h);
    cudaStreamWaitEvent(0, evT2, 0);
    gemm_mma_kernel<false><<<grid, THREADS, SMEM_BYTES>>>(
        0, (const __half*)p_h, (const __half*)p_wt2, b2, out);

    // expert 1 on s1 (trW1 already in-stream; needs gather + trW2)
    cudaStreamWaitEvent(s1, evG, 0);
    gemm_mma_kernel<true ><<<grid, THREADS, SMEM_BYTES, s1>>>(
        1, (const __half*)p_xg, (const __half*)p_wt1, b1, p_h);
    cudaStreamWaitEvent(s1, evT2, 0);
    gemm_mma_kernel<false><<<grid, THREADS, SMEM_BYTES, s1>>>(
        1, (const __half*)p_h, (const __half*)p_wt2, b2, out);
    cudaEventRecord(evE1, s1);

    // expert 2 on s2 (trW2 already in-stream; needs gather + trW1)
    cudaStreamWaitEvent(s2, evG, 0);
    cudaStreamWaitEvent(s2, evT1, 0);
    gemm_mma_kernel<true ><<<grid, THREADS, SMEM_BYTES, s2>>>(
        2, (const __half*)p_xg, (const __half*)p_wt1, b1, p_h);
    gemm_mma_kernel<false><<<grid, THREADS, SMEM_BYTES, s2>>>(
        2, (const __half*)p_h, (const __half*)p_wt2, b2, out);
    cudaEventRecord(evE2, s2);

    // join
    cudaStreamWaitEvent(0, evE1, 0);
    cudaStreamWaitEvent(0, evE2, 0);
}